// round 1
// baseline (speedup 1.0000x reference)
#include <cuda_runtime.h>
#include <math_constants.h>

#define NN    10000   // nodes
#define D     128     // feature dim
#define TOPK  8
#define DEG   32
#define OUTCH 128
#define INCH  9       // K+1
#define KS    9       // kernel size
#define XOUT  120     // D - K

__global__ __launch_bounds__(128)
void lgcl_fused_kernel(const float* __restrict__ nf,
                       const int*   __restrict__ adj,
                       const float* __restrict__ cw,
                       const float* __restrict__ cb,
                       float*       __restrict__ out)
{
    __shared__ float sel[INCH][D];   // row 0 = self, rows 1..8 = top-8 desc
    __shared__ int   nbrs[DEG];
    __shared__ int   cnt;

    const int n   = blockIdx.x;
    const int tid = threadIdx.x;     // 128 threads

    if (tid == 0) cnt = 0;
    if (tid < DEG) nbrs[tid] = 0;    // valid addresses even for padded slots
    __syncthreads();

    // ---- Phase A: scan adjacency row, compact neighbor indices ----
    // Row is 10000 int32 = 2500 int4, 16B-aligned (40000 % 16 == 0).
    {
        const int4* row4 = reinterpret_cast<const int4*>(adj + (size_t)n * NN);
        for (int i = tid; i < NN / 4; i += 128) {
            int4 v = row4[i];
            if (v.x | v.y | v.z | v.w) {
                if (v.x) nbrs[atomicAdd(&cnt, 1)] = 4 * i + 0;
                if (v.y) nbrs[atomicAdd(&cnt, 1)] = 4 * i + 1;
                if (v.z) nbrs[atomicAdd(&cnt, 1)] = 4 * i + 2;
                if (v.w) nbrs[atomicAdd(&cnt, 1)] = 4 * i + 3;
            }
        }
    }
    __syncthreads();
    const int m = cnt;   // number of real neighbors (<= 32, >= 1)

    // ---- Phase B: per-feature-column top-8 over neighbors ----
    {
        const int d = tid;           // column index, 0..127
        float tk[TOPK];
        #pragma unroll
        for (int s = 0; s < TOPK; s++) tk[s] = -CUDART_INF_F;

        #pragma unroll
        for (int j0 = 0; j0 < DEG; j0 += 8) {
            float v[8];
            #pragma unroll
            for (int u = 0; u < 8; u++) {
                int j = j0 + u;
                // predicated load: coalesced 512B per warp per neighbor row
                v[u] = (j < m) ? nf[(size_t)nbrs[j] * D + d] : -CUDART_INF_F;
            }
            #pragma unroll
            for (int u = 0; u < 8; u++) {
                float x = v[u];
                #pragma unroll
                for (int s = 0; s < TOPK; s++) {
                    float hi = fmaxf(tk[s], x);
                    x        = fminf(tk[s], x);
                    tk[s]    = hi;
                }
            }
        }
        // torch zero-pads missing neighbors before topk: insert (8-m) zeros
        for (int z = m; z < TOPK; z++) {
            float x = 0.0f;
            #pragma unroll
            for (int s = 0; s < TOPK; s++) {
                float hi = fmaxf(tk[s], x);
                x        = fminf(tk[s], x);
                tk[s]    = hi;
            }
        }

        sel[0][d] = nf[(size_t)n * D + d];   // self feature row
        #pragma unroll
        for (int s = 0; s < TOPK; s++) sel[1 + s][d] = tk[s];
    }
    __syncthreads();

    // ---- Phase C: Conv1d  out[n,o,x] = b[o] + sum_{c,t} sel[c][x+t]*w[o,c,t] ----
    {
        const int o = tid;           // output channel, 0..127
        float wr[INCH * KS];
        #pragma unroll
        for (int i = 0; i < INCH * KS; i++) wr[i] = cw[o * (INCH * KS) + i];
        const float bias = cb[o];

        float* op = out + ((size_t)n * OUTCH + o) * XOUT;   // 480B per o, 16B aligned

        for (int xb = 0; xb < XOUT; xb += 4) {
            float a0 = bias, a1 = bias, a2 = bias, a3 = bias;
            #pragma unroll
            for (int c = 0; c < INCH; c++) {
                // 12-wide window via three broadcast float4 LDS
                float4 wa = *reinterpret_cast<const float4*>(&sel[c][xb]);
                float4 wb = *reinterpret_cast<const float4*>(&sel[c][xb + 4]);
                float4 wc = *reinterpret_cast<const float4*>(&sel[c][xb + 8]);
                float win[12] = { wa.x, wa.y, wa.z, wa.w,
                                  wb.x, wb.y, wb.z, wb.w,
                                  wc.x, wc.y, wc.z, wc.w };
                #pragma unroll
                for (int t = 0; t < KS; t++) {
                    float wv = wr[c * KS + t];
                    a0 = fmaf(win[t + 0], wv, a0);
                    a1 = fmaf(win[t + 1], wv, a1);
                    a2 = fmaf(win[t + 2], wv, a2);
                    a3 = fmaf(win[t + 3], wv, a3);
                }
            }
            float4 r = make_float4(a0, a1, a2, a3);
            *reinterpret_cast<float4*>(op + xb) = r;
        }
    }
}

extern "C" void kernel_launch(void* const* d_in, const int* in_sizes, int n_in,
                              void* d_out, int out_size)
{
    const float* nf  = (const float*)d_in[0];   // [10000, 128]
    const int*   adj = (const int*)  d_in[1];   // [10000, 10000]
    const float* cw  = (const float*)d_in[2];   // [128, 9, 9]
    const float* cb  = (const float*)d_in[3];   // [128]
    float*       out = (float*)d_out;           // [10000, 128, 120]

    lgcl_fused_kernel<<<NN, 128>>>(nf, adj, cw, cb, out);
}

// round 3
// speedup vs baseline: 1.2239x; 1.2239x over previous
#include <cuda_runtime.h>
#include <math_constants.h>

#define NN    10000   // nodes
#define D     128     // feature dim
#define TOPK  8
#define DEG   32
#define OUTCH 128
#define INCH  9       // K+1
#define KS    9       // kernel size
#define XOUT  120     // D - K

// Prepacked weight pairs for packed-f32x2 conv:
//   k=0..4 (even-x set):  (w_{2k}, w_{2k+1}) with w9 := 0
//   k=5..9 (odd-x  set):  j=k-5: j==0 -> (0, w0) ; else (w_{2j-1}, w_{2j})
// Layout [c][k][o] so a warp's 32 consecutive o read 256B contiguous.
__device__ float2 g_wpre[INCH][10][OUTCH];

__global__ void prep_weights_kernel(const float* __restrict__ cw)
{
    int idx = blockIdx.x * blockDim.x + threadIdx.x;
    if (idx >= INCH * 10 * OUTCH) return;
    int o = idx % OUTCH;
    int k = (idx / OUTCH) % 10;
    int c = idx / (OUTCH * 10);
    const float* w = cw + (size_t)o * (INCH * KS) + c * KS;   // w[0..8]
    float2 v;
    if (k < 5) {
        v.x = w[2 * k];
        v.y = (2 * k + 1 < KS) ? w[2 * k + 1] : 0.0f;
    } else {
        int j = k - 5;
        if (j == 0) { v.x = 0.0f;          v.y = w[0];     }
        else        { v.x = w[2 * j - 1];  v.y = w[2 * j]; }
    }
    g_wpre[c][k][o] = v;
}

__device__ __forceinline__ unsigned long long ffma2(unsigned long long a,
                                                    unsigned long long b,
                                                    unsigned long long c)
{
    unsigned long long d;
    asm("fma.rn.f32x2 %0, %1, %2, %3;" : "=l"(d) : "l"(a), "l"(b), "l"(c));
    return d;
}

__global__ __launch_bounds__(128)
void lgcl_fused_kernel(const float* __restrict__ nf,
                       const int*   __restrict__ adj,
                       const float* __restrict__ cb,
                       float*       __restrict__ out)
{
    __shared__ __align__(16) float sel[INCH][D];  // row 0 = self, 1..8 = top-8 desc
    __shared__ int nbrs[DEG];
    __shared__ int cnt;

    const int n   = blockIdx.x;
    const int tid = threadIdx.x;     // 128 threads

    if (tid == 0) cnt = 0;
    if (tid < DEG) nbrs[tid] = 0;
    __syncthreads();

    // ---- Phase A: scan adjacency row, compact neighbor indices ----
    {
        const int4* row4 = reinterpret_cast<const int4*>(adj + (size_t)n * NN);
        for (int i = tid; i < NN / 4; i += 128) {
            int4 v = row4[i];
            if (v.x | v.y | v.z | v.w) {
                if (v.x) nbrs[atomicAdd(&cnt, 1)] = 4 * i + 0;
                if (v.y) nbrs[atomicAdd(&cnt, 1)] = 4 * i + 1;
                if (v.z) nbrs[atomicAdd(&cnt, 1)] = 4 * i + 2;
                if (v.w) nbrs[atomicAdd(&cnt, 1)] = 4 * i + 3;
            }
        }
    }
    __syncthreads();
    const int m = cnt;   // number of real neighbors (<= 32)

    // ---- Phase B: per-feature-column top-8 over neighbors ----
    {
        const int d = tid;           // column index, 0..127
        float tk[TOPK];
        #pragma unroll
        for (int s = 0; s < TOPK; s++) tk[s] = -CUDART_INF_F;

        #pragma unroll
        for (int j0 = 0; j0 < DEG; j0 += 8) {
            float v[8];
            #pragma unroll
            for (int u = 0; u < 8; u++) {
                int j = j0 + u;
                v[u] = (j < m) ? nf[(size_t)nbrs[j] * D + d] : -CUDART_INF_F;
            }
            #pragma unroll
            for (int u = 0; u < 8; u++) {
                float x = v[u];
                #pragma unroll
                for (int s = 0; s < TOPK; s++) {
                    float hi = fmaxf(tk[s], x);
                    x        = fminf(tk[s], x);
                    tk[s]    = hi;
                }
            }
        }
        // torch zero-pads missing neighbors before topk: insert (8-m) zeros
        for (int z = m; z < TOPK; z++) {
            float x = 0.0f;
            #pragma unroll
            for (int s = 0; s < TOPK; s++) {
                float hi = fmaxf(tk[s], x);
                x        = fminf(tk[s], x);
                tk[s]    = hi;
            }
        }

        sel[0][d] = nf[(size_t)n * D + d];
        #pragma unroll
        for (int s = 0; s < TOPK; s++) sel[1 + s][d] = tk[s];
    }
    __syncthreads();

    // ---- Phase C: Conv1d via packed fma.rn.f32x2 (tap-paired, parity trick) ----
    // out[o][x]  (x even) = sum_c sum_k (w2k,w2k+1).(win[x+2k],win[x+2k+1]),  w9=0
    // out[o][x+1]         = sum_c sum_k Wodd_k        .(same window pairs)
    // All window pairs sit at even float offsets -> direct broadcast LDS.64.
    {
        const int o = tid;           // output channel
        const float bias = cb[o];
        float* op = out + ((size_t)n * OUTCH + o) * XOUT;

        for (int cb0 = 0; cb0 < XOUT; cb0 += 24) {      // 5 chunks of 24 x
            unsigned long long acc[24];
            #pragma unroll
            for (int u = 0; u < 24; u++) acc[u] = 0ull;

            for (int c = 0; c < INCH; c++) {
                unsigned long long W[10];
                #pragma unroll
                for (int k = 0; k < 10; k++)
                    W[k] = *reinterpret_cast<const unsigned long long*>(&g_wpre[c][k][o]);

                const unsigned long long* Prow =
                    reinterpret_cast<const unsigned long long*>(&sel[c][0]);  // 64 pairs

                #pragma unroll
                for (int g = 0; g < 24; g += 8) {       // group: 8 x = 4 x-pairs
                    const int e0 = (cb0 + g) >> 1;
                    unsigned long long P[8];
                    #pragma unroll
                    for (int i = 0; i < 8; i++) P[i] = Prow[e0 + i];
                    #pragma unroll
                    for (int j = 0; j < 4; j++) {
                        #pragma unroll
                        for (int k = 0; k < 5; k++) {
                            acc[g + 2 * j]     = ffma2(P[j + k], W[k],     acc[g + 2 * j]);
                            acc[g + 2 * j + 1] = ffma2(P[j + k], W[5 + k], acc[g + 2 * j + 1]);
                        }
                    }
                }
            }

            // horizontal add + bias, vectorized store
            #pragma unroll
            for (int u = 0; u < 24; u += 4) {
                float2 a0 = *reinterpret_cast<float2*>(&acc[u + 0]);
                float2 a1 = *reinterpret_cast<float2*>(&acc[u + 1]);
                float2 a2 = *reinterpret_cast<float2*>(&acc[u + 2]);
                float2 a3 = *reinterpret_cast<float2*>(&acc[u + 3]);
                float4 r = make_float4(a0.x + a0.y + bias,
                                       a1.x + a1.y + bias,
                                       a2.x + a2.y + bias,
                                       a3.x + a3.y + bias);
                *reinterpret_cast<float4*>(op + cb0 + u) = r;
            }
        }
    }
}

extern "C" void kernel_launch(void* const* d_in, const int* in_sizes, int n_in,
                              void* d_out, int out_size)
{
    const float* nf  = (const float*)d_in[0];   // [10000, 128]
    const int*   adj = (const int*)  d_in[1];   // [10000, 10000]
    const float* cw  = (const float*)d_in[2];   // [128, 9, 9]
    const float* cb  = (const float*)d_in[3];   // [128]
    float*       out = (float*)d_out;           // [10000, 128, 120]

    prep_weights_kernel<<<(INCH * 10 * OUTCH + 127) / 128, 128>>>(cw);
    lgcl_fused_kernel<<<NN, 128>>>(nf, adj, cb, out);
}